// round 5
// baseline (speedup 1.0000x reference)
#include <cuda_runtime.h>
#include <cuda_fp16.h>
#include <cstdint>
#include <cstddef>

#define EMB    128
#define NCL    256
#define NROWS  200000
#define TILE_M 64
#define NT     3125             // ceil(200000/64)

// ---- smem layout (bytes), per CTA (2 CTAs/SM) ----
// B   : clusters fp16, 256 rows x 272B stride   [0,      69632)
// A   : X fp16 double buffer, 64 rows x 272B    [69632, 104448)
// ONEC: 1+||c||^2, 256 f32                      [104448, 105472)
// XSQ : ||x||^2, 2 x 64 f32                     [105472, 105984)
// PART: rowsum partials, 4 x 64 f32             [105984, 107008)
#define SB_OFF     0
#define SA_OFF     69632
#define A_BUF      17408
#define ONEC_OFF   104448
#define XSQ_OFF    105472
#define PART_OFF   105984
#define SMEM_TOTAL 107008

__device__ __forceinline__ void mma16816(float* d, const uint32_t* a,
                                         uint32_t b0, uint32_t b1) {
    asm volatile(
        "mma.sync.aligned.m16n8k16.row.col.f32.f16.f16.f32 "
        "{%0,%1,%2,%3},{%4,%5,%6,%7},{%8,%9},{%0,%1,%2,%3};\n"
        : "+f"(d[0]), "+f"(d[1]), "+f"(d[2]), "+f"(d[3])
        : "r"(a[0]), "r"(a[1]), "r"(a[2]), "r"(a[3]), "r"(b0), "r"(b1));
}

__device__ __forceinline__ uint32_t pack2(float a, float b) {
    __half2 h = __floats2half2_rn(a, b);
    return *reinterpret_cast<uint32_t*>(&h);
}

// Convert one 64-row X tile: fp32 gmem -> fp16 smem (272B stride) + ||x||^2.
// Thread t owns row r = t>>2, 32-float chunk s = t&3.
__device__ __forceinline__ void convert_a(char* smem, const float* __restrict__ x,
                                          int tile, int bufdst, int tid) {
    int r = tid >> 2, s = tid & 3;
    int grow = tile * TILE_M + r;
    char* dst = smem + SA_OFF + bufdst * A_BUF + r * 272 + s * 64;
    float acc = 0.f;
    if (grow < NROWS) {
        const float4* src =
            reinterpret_cast<const float4*>(x + (size_t)grow * EMB + s * 32);
        #pragma unroll
        for (int c = 0; c < 4; c++) {
            float4 fa = src[2 * c], fb = src[2 * c + 1];
            acc += fa.x * fa.x + fa.y * fa.y + fa.z * fa.z + fa.w * fa.w;
            acc += fb.x * fb.x + fb.y * fb.y + fb.z * fb.z + fb.w * fb.w;
            uint4 pk;
            pk.x = pack2(fa.x, fa.y); pk.y = pack2(fa.z, fa.w);
            pk.z = pack2(fb.x, fb.y); pk.w = pack2(fb.z, fb.w);
            *reinterpret_cast<uint4*>(dst + c * 16) = pk;
        }
    } else {
        uint4 z = make_uint4(0, 0, 0, 0);
        #pragma unroll
        for (int c = 0; c < 4; c++)
            *reinterpret_cast<uint4*>(dst + c * 16) = z;
    }
    acc += __shfl_xor_sync(0xffffffffu, acc, 1);
    acc += __shfl_xor_sync(0xffffffffu, acc, 2);
    if (s == 0)
        reinterpret_cast<float*>(smem + XSQ_OFF)[bufdst * TILE_M + r] = acc;
}

__global__ void __launch_bounds__(256, 2)
cluster_2cta_kernel(const float* __restrict__ x, const float* __restrict__ cl,
                    float* __restrict__ out) {
    extern __shared__ char smem[];
    const uint32_t sb = (uint32_t)__cvta_generic_to_shared(smem);
    const uint32_t sB = sb + SB_OFF;
    const uint32_t sA = sb + SA_OFF;
    float* onec_s = reinterpret_cast<float*>(smem + ONEC_OFF);
    float* xsq_s  = reinterpret_cast<float*>(smem + XSQ_OFF);
    float* part_s = reinterpret_cast<float*>(smem + PART_OFF);

    const int tid  = threadIdx.x;
    const int lane = tid & 31;
    const int wid  = tid >> 5;
    const int wm   = wid & 1;   // M group: 32 rows each
    const int wn   = wid >> 1;  // N group: 64 cols each
    const int grid = gridDim.x;
    const int bx   = blockIdx.x;

    // ---- prologue: clusters fp32 -> fp16 smem (272B stride) + 1+||c||^2 ----
    {
        int r = tid;   // one FULL row (128 floats -> 256B fp16) per thread
        const float4* src = reinterpret_cast<const float4*>(cl + (size_t)r * EMB);
        char* b = smem + SB_OFF + r * 272;
        float s = 0.f;
        #pragma unroll
        for (int c = 0; c < 16; c++) {
            float4 fa = src[2 * c], fb = src[2 * c + 1];
            s += fa.x * fa.x + fa.y * fa.y + fa.z * fa.z + fa.w * fa.w;
            s += fb.x * fb.x + fb.y * fb.y + fb.z * fb.z + fb.w * fb.w;
            uint4 pk;
            pk.x = pack2(fa.x, fa.y); pk.y = pack2(fa.z, fa.w);
            pk.z = pack2(fb.x, fb.y); pk.w = pack2(fb.z, fb.w);
            *reinterpret_cast<uint4*>(b + c * 16) = pk;
        }
        onec_s[r] = 1.0f + s;
    }
    convert_a(smem, x, bx, 0, tid);
    __syncthreads();

    const uint32_t bRowBase = wn * 64 + (lane & 7) + ((lane >> 4) << 3);
    const uint32_t bColByte = ((lane >> 3) & 1) * 16;

    int buf = 0;
    for (int tile = bx; tile < NT; tile += grid) {
        // ---- MMA on A[buf] ----
        const uint32_t sAc = sA + buf * A_BUF;
        float acc[2][8][4];
        #pragma unroll
        for (int mi = 0; mi < 2; mi++)
            #pragma unroll
            for (int ni = 0; ni < 8; ni++)
                #pragma unroll
                for (int e = 0; e < 4; e++) acc[mi][ni][e] = 0.f;

        const uint32_t aAddrBase =
            sAc + (wm * 32 + (lane & 15)) * 272 + (lane >> 4) * 16;

        #pragma unroll
        for (int kk = 0; kk < 8; kk++) {
            uint32_t a[2][4];
            #pragma unroll
            for (int mi = 0; mi < 2; mi++) {
                uint32_t addr = aAddrBase + mi * (16 * 272) + kk * 32;
                asm volatile(
                    "ldmatrix.sync.aligned.m8n8.x4.shared.b16 {%0,%1,%2,%3},[%4];\n"
                    : "=r"(a[mi][0]), "=r"(a[mi][1]), "=r"(a[mi][2]), "=r"(a[mi][3])
                    : "r"(addr) : "memory");
            }
            #pragma unroll
            for (int nj = 0; nj < 4; nj++) {
                uint32_t b0, b1, b2, b3;
                uint32_t addr = sB + (bRowBase + nj * 16) * 272 + bColByte + kk * 32;
                asm volatile(
                    "ldmatrix.sync.aligned.m8n8.x4.shared.b16 {%0,%1,%2,%3},[%4];\n"
                    : "=r"(b0), "=r"(b1), "=r"(b2), "=r"(b3)
                    : "r"(addr) : "memory");
                #pragma unroll
                for (int mi = 0; mi < 2; mi++) {
                    mma16816(acc[mi][2 * nj],     a[mi], b0, b1);
                    mma16816(acc[mi][2 * nj + 1], a[mi], b2, b3);
                }
            }
        }

        // ---- convert next tile into A[buf^1] (overlapped by co-resident CTA) ----
        int nxt = tile + grid;
        if (nxt < NT) convert_a(smem, x, nxt, buf ^ 1, tid);

        // ---- epilogue: q = 1/max(1+dist^2, 1); per-warp row partials ----
        float ocA[8], ocB[8];
        #pragma unroll
        for (int ni = 0; ni < 8; ni++) {
            float2 v = *reinterpret_cast<const float2*>(
                onec_s + wn * 64 + ni * 8 + (lane & 3) * 2);
            ocA[ni] = v.x; ocB[ni] = v.y;
        }
        float xv[2][2], part[2][2];
        #pragma unroll
        for (int mi = 0; mi < 2; mi++)
            #pragma unroll
            for (int h = 0; h < 2; h++) {
                int rl = wm * 32 + mi * 16 + (lane >> 2) + h * 8;
                xv[mi][h] = xsq_s[buf * TILE_M + rl];
                part[mi][h] = 0.f;
            }
        #pragma unroll
        for (int mi = 0; mi < 2; mi++)
            #pragma unroll
            for (int ni = 0; ni < 8; ni++)
                #pragma unroll
                for (int h = 0; h < 2; h++) {
                    float d0 = fmaxf(fmaf(-2.f, acc[mi][ni][2 * h + 0],
                                          xv[mi][h] + ocA[ni]), 1.0f);
                    float d1 = fmaxf(fmaf(-2.f, acc[mi][ni][2 * h + 1],
                                          xv[mi][h] + ocB[ni]), 1.0f);
                    float q0, q1;
                    asm("rcp.approx.f32 %0, %1;" : "=f"(q0) : "f"(d0));
                    asm("rcp.approx.f32 %0, %1;" : "=f"(q1) : "f"(d1));
                    acc[mi][ni][2 * h + 0] = q0;
                    acc[mi][ni][2 * h + 1] = q1;
                    part[mi][h] += q0 + q1;
                }
        #pragma unroll
        for (int mi = 0; mi < 2; mi++)
            #pragma unroll
            for (int h = 0; h < 2; h++) {
                float s = part[mi][h];
                s += __shfl_xor_sync(0xffffffffu, s, 1);
                s += __shfl_xor_sync(0xffffffffu, s, 2);
                if ((lane & 3) == 0) {
                    int rl = wm * 32 + mi * 16 + (lane >> 2) + h * 8;
                    part_s[wn * TILE_M + rl] = s;   // unique writer per (wn, rl)
                }
            }
        __syncthreads();   // S1: partials + A[buf^1]/xsq[buf^1] visible

        // ---- normalize + store ----
        #pragma unroll
        for (int mi = 0; mi < 2; mi++)
            #pragma unroll
            for (int h = 0; h < 2; h++) {
                int rl   = wm * 32 + mi * 16 + (lane >> 2) + h * 8;
                int grow = tile * TILE_M + rl;
                if (grow < NROWS) {
                    float tot = (part_s[rl] + part_s[64 + rl]) +
                                (part_s[128 + rl] + part_s[192 + rl]);
                    float inv;
                    asm("rcp.approx.f32 %0, %1;" : "=f"(inv) : "f"(tot));
                    float* op = out + (size_t)grow * NCL + wn * 64 + (lane & 3) * 2;
                    #pragma unroll
                    for (int ni = 0; ni < 8; ni++) {
                        float2 v = make_float2(acc[mi][ni][2 * h + 0] * inv,
                                               acc[mi][ni][2 * h + 1] * inv);
                        *reinterpret_cast<float2*>(op + ni * 8) = v;
                    }
                }
            }
        __syncthreads();   // S2: part_s reads done before next iter overwrites
        buf ^= 1;
    }
}

// ---------------- launcher ----------------

extern "C" void kernel_launch(void* const* d_in, const int* in_sizes, int n_in,
                              void* d_out, int out_size) {
    const float* x  = (const float*)d_in[0];
    const float* cl = (const float*)d_in[1];
    if (n_in >= 2 && in_sizes[0] == NCL * EMB) {  // defensive input-order check
        const float* t = x; x = cl; cl = t;
    }
    float* out = (float*)d_out;

    int sms = 148, dev = 0;
    if (cudaGetDevice(&dev) == cudaSuccess) {
        int v = 0;
        if (cudaDeviceGetAttribute(&v, cudaDevAttrMultiProcessorCount, dev) == cudaSuccess
            && v > 0) sms = v;
    }
    cudaFuncSetAttribute(cluster_2cta_kernel,
                         cudaFuncAttributeMaxDynamicSharedMemorySize, SMEM_TOTAL);
    cluster_2cta_kernel<<<2 * sms, 256, SMEM_TOTAL>>>(x, cl, out);
}

// round 6
// speedup vs baseline: 1.1863x; 1.1863x over previous
#include <cuda_runtime.h>
#include <cuda_fp16.h>
#include <cstdint>
#include <cstddef>

#define EMB   128
#define NCL   256
#define NROWS 200000
#define TILE_M 128
#define NT    1563              // ceil(200000/128)

// ---- smem layout (bytes) ----
// B   : clusters fp16, 256 rows x 272B stride      [0,      69632)
// A   : X fp16 double buffer, 128 rows x 272B each [69632, 139264)
// STG : fp32 staging, 128 rows x 512B (swizzled)   [139264, 204800)
// PART: partials, 2 x 4 x 128 f32                  [204800, 208896)
// XSQ : ||x||^2, 2 x 128 f32                       [208896, 209920)
// ONEC: 1+||c||^2, 256 f32                         [209920, 210944)
#define SB_OFF     0
#define SA_OFF     69632
#define A_BUF      34816
#define STG_OFF    139264
#define PART_OFF   204800
#define XSQ_OFF    208896
#define ONEC_OFF   209920
#define SMEM_TOTAL 210944

// staging address of 16B chunk g (0..31) of row r: XOR swizzle keeps both the
// cp.async stores and the strided float4 LDS (g = 4j + s) conflict-free.
__device__ __forceinline__ uint32_t stg_addr(uint32_t stg, int r, int g) {
    return stg + r * 512 + ((g ^ ((r & 7) << 2)) << 4);
}

__device__ __forceinline__ void cp16z(uint32_t dst, const void* src, int pbytes) {
    asm volatile("cp.async.cg.shared.global [%0], [%1], 16, %2;\n"
                 :: "r"(dst), "l"(src), "r"(pbytes) : "memory");
}

__device__ __forceinline__ void mma16816(float* d, const uint32_t* a,
                                         uint32_t b0, uint32_t b1) {
    asm volatile(
        "mma.sync.aligned.m16n8k16.row.col.f32.f16.f16.f32 "
        "{%0,%1,%2,%3},{%4,%5,%6,%7},{%8,%9},{%0,%1,%2,%3};\n"
        : "+f"(d[0]), "+f"(d[1]), "+f"(d[2]), "+f"(d[3])
        : "r"(a[0]), "r"(a[1]), "r"(a[2]), "r"(a[3]), "r"(b0), "r"(b1));
}

__device__ __forceinline__ uint32_t pack2(float a, float b) {
    __half2 h = __floats2half2_rn(a, b);
    return *reinterpret_cast<uint32_t*>(&h);
}

// Stage one 128-row fp32 tile into the swizzled staging buffer.
__device__ __forceinline__ void stage_tile(uint32_t stg, const float* __restrict__ x,
                                           int tt, int tid) {
    int r = tid >> 2, s = tid & 3;
    int grow = tt * TILE_M + r;
    int pb = (grow < NROWS) ? 16 : 0;
    int crow = (grow < NROWS) ? grow : (NROWS - 1);
    const float* src = x + (size_t)crow * EMB;
    #pragma unroll
    for (int j = 0; j < 8; j++) {
        int g = 4 * j + s;
        cp16z(stg_addr(stg, r, g), src + g * 4, pb);
    }
}

// Convert staged fp32 tile -> fp16 A buffer; also per-row ||x||^2.
__device__ __forceinline__ void convert_tile(char* smem, int dstbuf, int tid,
                                             float* __restrict__ xsq_dst) {
    int r = tid >> 2, s = tid & 3;
    const char* stg = smem + STG_OFF;
    char* a = smem + SA_OFF + dstbuf * A_BUF + r * 272;
    float acc = 0.f;
    #pragma unroll
    for (int j = 0; j < 8; j++) {
        int g = 4 * j + s;
        int so = r * 512 + ((g ^ ((r & 7) << 2)) << 4);
        float4 f = *reinterpret_cast<const float4*>(stg + so);
        acc += f.x * f.x + f.y * f.y + f.z * f.z + f.w * f.w;
        uint2 pk;
        pk.x = pack2(f.x, f.y);
        pk.y = pack2(f.z, f.w);
        *reinterpret_cast<uint2*>(a + g * 8) = pk;
    }
    acc += __shfl_xor_sync(0xffffffffu, acc, 1);
    acc += __shfl_xor_sync(0xffffffffu, acc, 2);
    if (s == 0) xsq_dst[r] = acc;
}

__global__ void __launch_bounds__(512, 1)
cluster_fused_kernel(const float* __restrict__ x, const float* __restrict__ cl,
                     float* __restrict__ out) {
    extern __shared__ char smem[];
    const uint32_t sb   = (uint32_t)__cvta_generic_to_shared(smem);
    const uint32_t sB   = sb + SB_OFF;
    const uint32_t sA   = sb + SA_OFF;
    const uint32_t sSTG = sb + STG_OFF;
    float* part_s = reinterpret_cast<float*>(smem + PART_OFF);   // [2][4][128]
    float* xsq_s  = reinterpret_cast<float*>(smem + XSQ_OFF);    // [2][128]
    float* onec_s = reinterpret_cast<float*>(smem + ONEC_OFF);   // [256]

    const int tid  = threadIdx.x;
    const int lane = tid & 31;
    const int wid  = tid >> 5;
    const int wm   = wid & 3;   // warp row 0..3 (32 rows each)
    const int wn   = wid >> 2;  // warp col 0..3 (64 cols each)
    const int grid = gridDim.x;

    int tile = blockIdx.x;

    // ---- prologue: stage tile0 (async), convert clusters meanwhile ----
    stage_tile(sSTG, x, tile, tid);
    asm volatile("cp.async.commit_group;\n" ::: "memory");

    {   // clusters fp32 -> fp16 smem B (272B row stride) + 1+||c||^2
        int row = tid >> 1, half = tid & 1;
        const float4* src = reinterpret_cast<const float4*>(cl + row * EMB + half * 64);
        char* b = smem + SB_OFF + row * 272 + half * 128;
        float s = 0.f;
        #pragma unroll
        for (int c = 0; c < 8; c++) {
            float4 fa = src[2 * c], fb = src[2 * c + 1];
            s += fa.x * fa.x + fa.y * fa.y + fa.z * fa.z + fa.w * fa.w;
            s += fb.x * fb.x + fb.y * fb.y + fb.z * fb.z + fb.w * fb.w;
            uint4 pk;
            pk.x = pack2(fa.x, fa.y); pk.y = pack2(fa.z, fa.w);
            pk.z = pack2(fb.x, fb.y); pk.w = pack2(fb.z, fb.w);
            *reinterpret_cast<uint4*>(b + c * 16) = pk;
        }
        s += __shfl_xor_sync(0xffffffffu, s, 1);
        if (half == 0) onec_s[row] = 1.0f + s;
    }

    asm volatile("cp.async.wait_group 0;\n" ::: "memory");
    convert_tile(smem, 0, tid, xsq_s);          // tile0 -> A[0], xsq[0]
    if (tile + grid < NT) {
        stage_tile(sSTG, x, tile + grid, tid);
        asm volatile("cp.async.commit_group;\n" ::: "memory");
    }
    __syncthreads();    // B, onec, A[0], xsq[0] visible

    // Per-thread 1+||c||^2 registers (columns fixed across tiles).
    float ocA[8], ocB[8];
    #pragma unroll
    for (int ni = 0; ni < 8; ni++) {
        int n0 = wn * 64 + ni * 8 + (lane & 3) * 2;
        ocA[ni] = onec_s[n0];
        ocB[ni] = onec_s[n0 + 1];
    }

    const uint32_t bRowBase = wn * 64 + (lane & 7) + ((lane >> 4) << 3);
    const uint32_t bColByte = ((lane >> 3) & 1) * 16;

    int buf = 0, pb = 0;
    for (; tile < NT; tile += grid) {
        // ---- MMA on A[buf] ----
        const uint32_t sAc = sA + buf * A_BUF;
        float acc[2][8][4];
        #pragma unroll
        for (int mi = 0; mi < 2; mi++)
            #pragma unroll
            for (int ni = 0; ni < 8; ni++)
                #pragma unroll
                for (int e = 0; e < 4; e++) acc[mi][ni][e] = 0.f;

        const uint32_t aAddrBase =
            sAc + (wm * 32 + (lane & 15)) * 272 + (lane >> 4) * 16;

        #pragma unroll
        for (int kk = 0; kk < 8; kk++) {
            uint32_t a[2][4];
            #pragma unroll
            for (int mi = 0; mi < 2; mi++) {
                uint32_t addr = aAddrBase + mi * (16 * 272) + kk * 32;
                asm volatile(
                    "ldmatrix.sync.aligned.m8n8.x4.shared.b16 {%0,%1,%2,%3},[%4];\n"
                    : "=r"(a[mi][0]), "=r"(a[mi][1]), "=r"(a[mi][2]), "=r"(a[mi][3])
                    : "r"(addr) : "memory");
            }
            #pragma unroll
            for (int nj = 0; nj < 4; nj++) {
                uint32_t b0, b1, b2, b3;
                uint32_t addr = sB + (bRowBase + nj * 16) * 272 + bColByte + kk * 32;
                asm volatile(
                    "ldmatrix.sync.aligned.m8n8.x4.shared.b16 {%0,%1,%2,%3},[%4];\n"
                    : "=r"(b0), "=r"(b1), "=r"(b2), "=r"(b3)
                    : "r"(addr) : "memory");
                #pragma unroll
                for (int mi = 0; mi < 2; mi++) {
                    mma16816(acc[mi][2 * nj],     a[mi], b0, b1);
                    mma16816(acc[mi][2 * nj + 1], a[mi], b2, b3);
                }
            }
        }

        // ---- pipeline: convert next tile (A[buf^1]) & stage tile after next ----
        int nxt = tile + grid;
        if (nxt < NT) {
            asm volatile("cp.async.wait_group 0;\n" ::: "memory");
            convert_tile(smem, buf ^ 1, tid, xsq_s + (buf ^ 1) * 128);
            int nn = nxt + grid;
            if (nn < NT) {
                stage_tile(sSTG, x, nn, tid);
                asm volatile("cp.async.commit_group;\n" ::: "memory");
            }
        }

        // ---- epilogue: q = 1/max(1+dist^2, 1); per-warp row partials ----
        const float* xsq_cur = xsq_s + buf * 128;
        float xv[2][2], part[2][2];
        #pragma unroll
        for (int mi = 0; mi < 2; mi++)
            #pragma unroll
            for (int h = 0; h < 2; h++) {
                int rl = wm * 32 + mi * 16 + (lane >> 2) + h * 8;
                xv[mi][h] = xsq_cur[rl];
                part[mi][h] = 0.f;
            }
        #pragma unroll
        for (int mi = 0; mi < 2; mi++)
            #pragma unroll
            for (int ni = 0; ni < 8; ni++)
                #pragma unroll
                for (int h = 0; h < 2; h++) {
                    float d0 = fmaxf(fmaf(-2.f, acc[mi][ni][2 * h + 0],
                                          xv[mi][h] + ocA[ni]), 1.0f);
                    float d1 = fmaxf(fmaf(-2.f, acc[mi][ni][2 * h + 1],
                                          xv[mi][h] + ocB[ni]), 1.0f);
                    float q0, q1;
                    asm("rcp.approx.f32 %0, %1;" : "=f"(q0) : "f"(d0));
                    asm("rcp.approx.f32 %0, %1;" : "=f"(q1) : "f"(d1));
                    acc[mi][ni][2 * h + 0] = q0;
                    acc[mi][ni][2 * h + 1] = q1;
                    part[mi][h] += q0 + q1;
                }
        float* pdst = part_s + pb * 512 + wn * 128;
        #pragma unroll
        for (int mi = 0; mi < 2; mi++)
            #pragma unroll
            for (int h = 0; h < 2; h++) {
                float s = part[mi][h];
                s += __shfl_xor_sync(0xffffffffu, s, 1);
                s += __shfl_xor_sync(0xffffffffu, s, 2);
                if ((lane & 3) == 0) {
                    int rl = wm * 32 + mi * 16 + (lane >> 2) + h * 8;
                    pdst[rl] = s;   // unique writer per (wn, row)
                }
            }
        __syncthreads();   // ONLY barrier: partials + A[buf^1]/xsq[buf^1] visible

        // ---- normalize + store (flows into next tile's MMA, no barrier) ----
        const float* psrc = part_s + pb * 512;
        #pragma unroll
        for (int mi = 0; mi < 2; mi++)
            #pragma unroll
            for (int h = 0; h < 2; h++) {
                int rl   = wm * 32 + mi * 16 + (lane >> 2) + h * 8;
                int grow = tile * TILE_M + rl;
                if (grow < NROWS) {
                    float tot = (psrc[rl] + psrc[128 + rl]) +
                                (psrc[256 + rl] + psrc[384 + rl]);
                    float inv;
                    asm("rcp.approx.f32 %0, %1;" : "=f"(inv) : "f"(tot));
                    float* op = out + (size_t)grow * NCL + wn * 64 + (lane & 3) * 2;
                    #pragma unroll
                    for (int ni = 0; ni < 8; ni++) {
                        float2 v = make_float2(acc[mi][ni][2 * h + 0] * inv,
                                               acc[mi][ni][2 * h + 1] * inv);
                        *reinterpret_cast<float2*>(op + ni * 8) = v;
                    }
                }
            }
        buf ^= 1;
        pb ^= 1;
    }
}

// ---------------- launcher ----------------

extern "C" void kernel_launch(void* const* d_in, const int* in_sizes, int n_in,
                              void* d_out, int out_size) {
    const float* x  = (const float*)d_in[0];
    const float* cl = (const float*)d_in[1];
    if (n_in >= 2 && in_sizes[0] == NCL * EMB) {  // defensive input-order check
        const float* t = x; x = cl; cl = t;
    }
    float* out = (float*)d_out;

    int sms = 148, dev = 0;
    if (cudaGetDevice(&dev) == cudaSuccess) {
        int v = 0;
        if (cudaDeviceGetAttribute(&v, cudaDevAttrMultiProcessorCount, dev) == cudaSuccess
            && v > 0) sms = v;
    }
    cudaFuncSetAttribute(cluster_fused_kernel,
                         cudaFuncAttributeMaxDynamicSharedMemorySize, SMEM_TOTAL);
    cluster_fused_kernel<<<sms, 512, SMEM_TOTAL>>>(x, cl, out);
}